// round 7
// baseline (speedup 1.0000x reference)
#include <cuda_runtime.h>
#include <math.h>

#define N_NODES 25600
#define N_EDGES 204800
#define ETOT    (N_EDGES + N_NODES)   // 230400
#define IN_CH   6
#define HID     64
#define HEADS   4
#define C1      (HEADS*HID)           // 256
#define G_GRAPHS 512
#define T_STEPS  50
#define OUT_DIM  30
#define NEG_SLOPE 0.2f
#define BN_INV 0.9999950000374996f    // 1/sqrt(1+1e-5)

// ---------------- scratch ----------------
__device__ float g_wsrc[24];                  // [k][h]
__device__ float g_wdst[24];
__device__ __align__(16) float g_x8[N_NODES*8];       // padded x rows
__device__ __align__(16) float g_asrc1[N_NODES*4];
__device__ __align__(16) float g_adst1[N_NODES*4];
__device__ __align__(16) float g_xagg[N_NODES*32];    // 4 heads x [x0..x5, denom, 0]
__device__ __align__(16) float g_hproj2[N_NODES*HID];
__device__ float g_asrc2[N_NODES];
__device__ float g_adst2[N_NODES];
__device__ float g_denom2[N_NODES];
__device__ __align__(16) float g_accum2[N_NODES*HID];
__device__ __align__(16) float g_xgates[N_NODES*C1];  // (t, g, 256)

// ---------------- helpers ----------------
__device__ __forceinline__ float lrelu(float v) { return v > 0.f ? v : NEG_SLOPE*v; }
__device__ __forceinline__ float eluf(float v)  { return v > 0.f ? v : (__expf(v) - 1.f); }
__device__ __forceinline__ float sigf(float v)  { return 1.f/(1.f+expf(-v)); }

__device__ __forceinline__ void redAdd4(float* addr, float a, float b, float c, float d) {
    asm volatile("red.global.add.v4.f32 [%0], {%1,%2,%3,%4};"
                 :: "l"(addr), "f"(a), "f"(b), "f"(c), "f"(d) : "memory");
}
__device__ __forceinline__ void ffma2(unsigned long long& d, unsigned long long a,
                                      unsigned long long b) {
    asm("fma.rn.f32x2 %0, %1, %2, %0;" : "+l"(d) : "l"(a), "l"(b));
}
__device__ __forceinline__ unsigned long long pk(float a, float b) {
    unsigned long long r;
    asm("mov.b64 %0, {%1, %2};" : "=l"(r) : "f"(a), "f"(b));
    return r;
}
__device__ __forceinline__ float2 unpk(unsigned long long v) {
    float2 r;
    asm("mov.b64 {%0, %1}, %2;" : "=f"(r.x), "=f"(r.y) : "l"(v));
    return r;
}

// ---------------- kernels ----------------
__global__ void k_pre1(const float* __restrict__ W1, const float* __restrict__ as1,
                       const float* __restrict__ ad1) {
    int t = threadIdx.x;
    if (t < 24) {
        int k = t >> 2, h = t & 3;
        float s = 0.f;
        for (int c = 0; c < 64; c++) s += W1[k*C1 + h*64 + c] * as1[h*64 + c];
        g_wsrc[t] = s;
    } else if (t >= 32 && t < 56) {
        int i = t - 32, k = i >> 2, h = i & 3;
        float s = 0.f;
        for (int c = 0; c < 64; c++) s += W1[k*C1 + h*64 + c] * ad1[h*64 + c];
        g_wdst[i] = s;
    }
}

__global__ void k_att1(const float* __restrict__ x) {
    int n = blockIdx.x*blockDim.x + threadIdx.x;
    if (n >= N_NODES) return;
    float2 xa = *(const float2*)&x[n*6];
    float2 xb = *(const float2*)&x[n*6 + 2];
    float2 xc = *(const float2*)&x[n*6 + 4];
    float xv[6] = {xa.x, xa.y, xb.x, xb.y, xc.x, xc.y};
    float s[4] = {0,0,0,0}, d[4] = {0,0,0,0};
    #pragma unroll
    for (int k = 0; k < 6; k++) {
        #pragma unroll
        for (int h = 0; h < 4; h++) {
            s[h] += xv[k]*g_wsrc[k*4+h];
            d[h] += xv[k]*g_wdst[k*4+h];
        }
    }
    *(float4*)&g_asrc1[n*4] = make_float4(s[0],s[1],s[2],s[3]);
    *(float4*)&g_adst1[n*4] = make_float4(d[0],d[1],d[2],d[3]);
    *(float4*)&g_x8[n*8]     = make_float4(xv[0],xv[1],xv[2],xv[3]);
    *(float4*)&g_x8[n*8 + 4] = make_float4(xv[4],xv[5],0.f,0.f);
}

__global__ void k_esum1(const int* __restrict__ ei) {
    int e = blockIdx.x*blockDim.x + threadIdx.x;
    if (e >= ETOT) return;
    int s, d;
    if (e < N_EDGES) { s = ei[e]; d = ei[N_EDGES + e]; } else { s = d = e - N_EDGES; }
    float4 as = *(const float4*)&g_asrc1[s*4];
    float4 ad = *(const float4*)&g_adst1[d*4];
    float ex[4];
    ex[0] = expf(lrelu(as.x + ad.x));
    ex[1] = expf(lrelu(as.y + ad.y));
    ex[2] = expf(lrelu(as.z + ad.z));
    ex[3] = expf(lrelu(as.w + ad.w));
    float4 xa = *(const float4*)&g_x8[s*8];
    float4 xb = *(const float4*)&g_x8[s*8 + 4];
    float* base = &g_xagg[d*32];
    #pragma unroll
    for (int h = 0; h < 4; h++) {
        float w = ex[h];
        redAdd4(base + h*8,     w*xa.x, w*xa.y, w*xa.z, w*xa.w);
        redAdd4(base + h*8 + 4, w*xb.x, w*xb.y, w,      0.f);
    }
}

// fused: h1 = elu(bn(xagg@W1/denom)); hproj2 = h1@W2; att2 dots.
// One node per thread; 64 plain-float accumulators; weights broadcast from smem.
__global__ void __launch_bounds__(128, 3) k_proj2f(
        const float* __restrict__ W1, const float* __restrict__ b1,
        const float* __restrict__ g1, const float* __restrict__ be1,
        const float* __restrict__ W2,
        const float* __restrict__ as2, const float* __restrict__ ad2) {
    extern __shared__ float sm[];
    float* sW2  = sm;                  // [256][64] = 16384
    float* sW1t = sm + 16384;          // [256][6]  = 1536 (W1 transposed)
    float* sB   = sW1t + 1536;         // 256: b1
    float* sG   = sB + 256;            // 256: g1*BN_INV
    float* sBe  = sG + 256;            // 256: be1
    float* sAs  = sBe + 256;           // 64
    float* sAd  = sAs + 64;            // 64
    int t = threadIdx.x;

    for (int i = t; i < 16384; i += 128) sW2[i] = W2[i];
    for (int i = t; i < 1536; i += 128) { int k = i >> 3; int r = i & 7;  // pack 6-wide
        ; }
    // W1 transpose: W1 is [6][256]; store sW1t[k*6 + r] = W1[r*256 + k]
    for (int i = t; i < 256*6; i += 128) {
        int k = i / 6, r = i % 6;
        sW1t[k*6 + r] = W1[r*C1 + k];
    }
    for (int i = t; i < 256; i += 128) {
        sB[i]  = b1[i];
        sG[i]  = g1[i]*BN_INV;
        sBe[i] = be1[i];
    }
    if (t < 64) { sAs[t] = as2[t]; sAd[t] = ad2[t]; }
    __syncthreads();

    int n = blockIdx.x*128 + t;
    // load xagg row into registers
    float xr[32];
    #pragma unroll
    for (int i = 0; i < 8; i++) {
        float4 v = *(const float4*)&g_xagg[n*32 + i*4];
        xr[i*4+0] = v.x; xr[i*4+1] = v.y; xr[i*4+2] = v.z; xr[i*4+3] = v.w;
    }
    #pragma unroll
    for (int h = 0; h < 4; h++) xr[h*8 + 6] = 1.f / xr[h*8 + 6];   // hoisted rcp

    float acc[64];
    #pragma unroll
    for (int j = 0; j < 64; j++) acc[j] = 0.f;

    #pragma unroll
    for (int h = 0; h < 4; h++) {
        #pragma unroll 2
        for (int k2 = 0; k2 < 64; k2++) {
            int k = h*64 + k2;
            const float* wk = &sW1t[k*6];
            float v = xr[h*8+0]*wk[0] + xr[h*8+1]*wk[1] + xr[h*8+2]*wk[2]
                    + xr[h*8+3]*wk[3] + xr[h*8+4]*wk[4] + xr[h*8+5]*wk[5];
            v = v*xr[h*8+6] + sB[k];
            v = eluf(sG[k]*v + sBe[k]);
            const float4* wr = (const float4*)&sW2[k*64];
            #pragma unroll
            for (int j4 = 0; j4 < 16; j4++) {
                float4 w = wr[j4];
                acc[4*j4+0] = fmaf(v, w.x, acc[4*j4+0]);
                acc[4*j4+1] = fmaf(v, w.y, acc[4*j4+1]);
                acc[4*j4+2] = fmaf(v, w.z, acc[4*j4+2]);
                acc[4*j4+3] = fmaf(v, w.w, acc[4*j4+3]);
            }
        }
    }

    float s = 0.f, dd = 0.f;
    #pragma unroll
    for (int j4 = 0; j4 < 16; j4++) {
        *(float4*)&g_hproj2[n*64 + j4*4] =
            make_float4(acc[4*j4], acc[4*j4+1], acc[4*j4+2], acc[4*j4+3]);
        #pragma unroll
        for (int u = 0; u < 4; u++) {
            s  += acc[4*j4+u]*sAs[4*j4+u];
            dd += acc[4*j4+u]*sAd[4*j4+u];
        }
    }
    g_asrc2[n] = s;
    g_adst2[n] = dd;
}

// 8 threads/edge: denom += ex; accum2[dst] += ex*hproj2[src]
__global__ void k_esum2(const int* __restrict__ ei) {
    int gt = blockIdx.x*blockDim.x + threadIdx.x;
    int e = gt >> 3, q = gt & 7;
    if (e >= ETOT) return;
    int s, d;
    if (e < N_EDGES) { s = ei[e]; d = ei[N_EDGES + e]; } else { s = d = e - N_EDGES; }
    float ex = expf(lrelu(g_asrc2[s] + g_adst2[d]));
    if (q == 0) atomicAdd(&g_denom2[d], ex);
    int c = q*8;
    float4 v1 = *(const float4*)&g_hproj2[s*64 + c];
    float4 v2 = *(const float4*)&g_hproj2[s*64 + c + 4];
    redAdd4(&g_accum2[d*64 + c],     v1.x*ex, v1.y*ex, v1.z*ex, v1.w*ex);
    redAdd4(&g_accum2[d*64 + c + 4], v2.x*ex, v2.y*ex, v2.z*ex, v2.w*ex);
}

// fused: h2 = elu(bn(accum2/denom2)); xgates = h2@Wih^T + biases (scattered).
// One node per thread; 4 column-chunk passes of 64 accumulators each.
__global__ void __launch_bounds__(128, 3) k_xgates2(
        const float* __restrict__ Wih, const float* __restrict__ bih,
        const float* __restrict__ bhh, const float* __restrict__ b2,
        const float* __restrict__ g2, const float* __restrict__ be2,
        const int* __restrict__ batch, const int* __restrict__ ntime) {
    extern __shared__ float sm[];
    float* sWT  = sm;                  // [64 k][256 j] = Wih^T, 16384
    float* sBias= sm + 16384;          // 256: bih+bhh
    float* sB2  = sBias + 256;         // 64
    float* sG2  = sB2 + 64;            // 64
    float* sBe2 = sG2 + 64;            // 64
    int t = threadIdx.x;

    for (int i = t; i < 16384; i += 128) {
        int j = i >> 6, k = i & 63;
        sWT[k*256 + j] = Wih[i];
    }
    for (int i = t; i < 256; i += 128) sBias[i] = bih[i] + bhh[i];
    if (t < 64) { sB2[t] = b2[t]; sG2[t] = g2[t]*BN_INV; sBe2[t] = be2[t]; }
    __syncthreads();

    int n = blockIdx.x*128 + t;
    float inv = 1.f / g_denom2[n];
    const float* arow = &g_accum2[n*64];
    int dest = (ntime[n]*G_GRAPHS + batch[n])*C1;

    #pragma unroll
    for (int jc = 0; jc < 4; jc++) {
        float acc[64];
        #pragma unroll
        for (int j = 0; j < 64; j++) acc[j] = 0.f;
        #pragma unroll 2
        for (int k = 0; k < 64; k++) {
            float v = arow[k]*inv + sB2[k];
            v = eluf(sG2[k]*v + sBe2[k]);
            const float4* wr = (const float4*)&sWT[k*256 + jc*64];
            #pragma unroll
            for (int j4 = 0; j4 < 16; j4++) {
                float4 w = wr[j4];
                acc[4*j4+0] = fmaf(v, w.x, acc[4*j4+0]);
                acc[4*j4+1] = fmaf(v, w.y, acc[4*j4+1]);
                acc[4*j4+2] = fmaf(v, w.z, acc[4*j4+2]);
                acc[4*j4+3] = fmaf(v, w.w, acc[4*j4+3]);
            }
        }
        #pragma unroll
        for (int j4 = 0; j4 < 16; j4++) {
            int j = jc*64 + j4*4;
            *(float4*)&g_xgates[dest + j] =
                make_float4(acc[4*j4]+sBias[j],   acc[4*j4+1]+sBias[j+1],
                            acc[4*j4+2]+sBias[j+2], acc[4*j4+3]+sBias[j+3]);
        }
    }
}

// LSTM: 1 graph/block (512 blocks), Whh row in regs, xgates prefetch, fused FC.
__global__ void __launch_bounds__(256) k_lstm(
        const float* __restrict__ Whh, const float* __restrict__ Wfc,
        const float* __restrict__ bfc, float* __restrict__ out) {
    __shared__ float hhs[64];
    __shared__ float gates[C1];
    int t = threadIdx.x;
    int g = blockIdx.x;

    unsigned long long w2[32];
    const float4* wrow = (const float4*)(Whh + t*64);
    #pragma unroll
    for (int i = 0; i < 16; i++) {
        float4 w = wrow[i];
        w2[2*i]   = pk(w.x, w.y);
        w2[2*i+1] = pk(w.z, w.w);
    }
    if (t < 64) hhs[t] = 0.f;
    float c = 0.f;
    float xg_cur = g_xgates[g*C1 + t];
    __syncthreads();

    for (int step = 0; step < T_STEPS; step++) {
        float xg_next = 0.f;
        if (step + 1 < T_STEPS) xg_next = g_xgates[((step+1)*G_GRAPHS + g)*C1 + t];
        unsigned long long aA = 0ull, aB = 0ull;
        #pragma unroll
        for (int k2 = 0; k2 < 16; k2++) {
            ulonglong2 hv = *(const ulonglong2*)&hhs[k2*4];
            ffma2(aA, hv.x, w2[2*k2]);
            ffma2(aB, hv.y, w2[2*k2+1]);
        }
        float2 a = unpk(aA), b = unpk(aB);
        gates[t] = xg_cur + a.x + a.y + b.x + b.y;
        __syncthreads();
        if (t < 64) {
            float ig = gates[t],       fg = gates[64 + t];
            float gg = gates[128 + t], og = gates[192 + t];
            c = sigf(fg)*c + sigf(ig)*tanhf(gg);
            hhs[t] = sigf(og)*tanhf(c);
        }
        __syncthreads();
        xg_cur = xg_next;
    }
    if (t < OUT_DIM) {
        float acc = bfc[t];
        #pragma unroll 8
        for (int k = 0; k < 64; k++) acc += hhs[k] * Wfc[k*OUT_DIM + t];
        out[g*OUT_DIM + t] = acc;
    }
}

// ---------------- launch ----------------
static const int SMEM_P2 = (16384 + 1536 + 256*3 + 128) * 4;   // ~74.3 KB
static const int SMEM_XG = (16384 + 256 + 64*3) * 4;           // ~66.3 KB

extern "C" void kernel_launch(void* const* d_in, const int* in_sizes, int n_in,
                              void* d_out, int out_size) {
    const float* x    = (const float*)d_in[0];
    const int*   ei   = (const int*)  d_in[1];
    const int*   batch= (const int*)  d_in[2];
    const int*   ntime= (const int*)  d_in[3];
    const float* W1   = (const float*)d_in[4];
    const float* as1  = (const float*)d_in[5];
    const float* ad1  = (const float*)d_in[6];
    const float* b1   = (const float*)d_in[7];
    const float* g1   = (const float*)d_in[8];
    const float* be1  = (const float*)d_in[9];
    const float* W2   = (const float*)d_in[10];
    const float* as2  = (const float*)d_in[11];
    const float* ad2  = (const float*)d_in[12];
    const float* b2   = (const float*)d_in[13];
    const float* g2   = (const float*)d_in[14];
    const float* be2  = (const float*)d_in[15];
    const float* Wih  = (const float*)d_in[16];
    const float* Whh  = (const float*)d_in[17];
    const float* bih  = (const float*)d_in[18];
    const float* bhh  = (const float*)d_in[19];
    const float* Wfc  = (const float*)d_in[20];
    const float* bfc  = (const float*)d_in[21];
    float* out = (float*)d_out;

    cudaFuncSetAttribute(k_proj2f,  cudaFuncAttributeMaxDynamicSharedMemorySize, SMEM_P2);
    cudaFuncSetAttribute(k_xgates2, cudaFuncAttributeMaxDynamicSharedMemorySize, SMEM_XG);

    void *p_xagg, *p_acc2, *p_den2;
    cudaGetSymbolAddress(&p_xagg, g_xagg);
    cudaGetSymbolAddress(&p_acc2, g_accum2);
    cudaGetSymbolAddress(&p_den2, g_denom2);
    cudaMemsetAsync(p_xagg, 0, sizeof(float)*N_NODES*32);
    cudaMemsetAsync(p_acc2, 0, sizeof(float)*N_NODES*HID);
    cudaMemsetAsync(p_den2, 0, sizeof(float)*N_NODES);

    k_pre1   <<<1, 64>>>(W1, as1, ad1);
    k_att1   <<<(N_NODES + 255)/256, 256>>>(x);
    k_esum1  <<<(ETOT + 255)/256, 256>>>(ei);
    k_proj2f <<<N_NODES/128, 128, SMEM_P2>>>(W1, b1, g1, be1, W2, as2, ad2);
    k_esum2  <<<(ETOT*8 + 255)/256, 256>>>(ei);
    k_xgates2<<<N_NODES/128, 128, SMEM_XG>>>(Wih, bih, bhh, b2, g2, be2, batch, ntime);
    k_lstm   <<<G_GRAPHS, 256>>>(Whh, Wfc, bfc, out);
}

// round 8
// speedup vs baseline: 1.0352x; 1.0352x over previous
#include <cuda_runtime.h>
#include <math.h>

#define N_NODES 25600
#define N_EDGES 204800
#define ETOT    (N_EDGES + N_NODES)   // 230400
#define IN_CH   6
#define HID     64
#define HEADS   4
#define C1      (HEADS*HID)           // 256
#define G_GRAPHS 512
#define T_STEPS  50
#define OUT_DIM  30
#define NEG_SLOPE 0.2f
#define BN_INV 0.9999950000374996f    // 1/sqrt(1+1e-5)

// ---------------- scratch ----------------
__device__ float g_wsrc[24];                  // [k][h]
__device__ float g_wdst[24];
__device__ __align__(16) float g_x8[N_NODES*8];       // padded x rows
__device__ __align__(16) float g_asrc1[N_NODES*4];
__device__ __align__(16) float g_adst1[N_NODES*4];
__device__ __align__(16) float g_xagg[N_NODES*32];    // 4 heads x [x0..x5, denom, 0]
__device__ __align__(16) float g_hproj2[N_NODES*HID];
__device__ float g_asrc2[N_NODES];
__device__ float g_adst2[N_NODES];
__device__ float g_denom2[N_NODES];
__device__ __align__(16) float g_accum2[N_NODES*HID];
__device__ __align__(16) float g_xgates[N_NODES*C1];  // (t, g, 256)

// ---------------- helpers ----------------
__device__ __forceinline__ float lrelu(float v) { return v > 0.f ? v : NEG_SLOPE*v; }
__device__ __forceinline__ float eluf(float v)  { return v > 0.f ? v : (__expf(v) - 1.f); }
__device__ __forceinline__ float sigf(float v)  { return 1.f/(1.f+expf(-v)); }

__device__ __forceinline__ void redAdd4(float* addr, float a, float b, float c, float d) {
    asm volatile("red.global.add.v4.f32 [%0], {%1,%2,%3,%4};"
                 :: "l"(addr), "f"(a), "f"(b), "f"(c), "f"(d) : "memory");
}
__device__ __forceinline__ void ffma2(unsigned long long& d, unsigned long long a,
                                      unsigned long long b) {
    asm("fma.rn.f32x2 %0, %1, %2, %0;" : "+l"(d) : "l"(a), "l"(b));
}
__device__ __forceinline__ unsigned long long pk(float a, float b) {
    unsigned long long r;
    asm("mov.b64 %0, {%1, %2};" : "=l"(r) : "f"(a), "f"(b));
    return r;
}
__device__ __forceinline__ float2 unpk(unsigned long long v) {
    float2 r;
    asm("mov.b64 {%0, %1}, %2;" : "=f"(r.x), "=f"(r.y) : "l"(v));
    return r;
}

// ---------------- kernels ----------------
__global__ void k_pre1(const float* __restrict__ W1, const float* __restrict__ as1,
                       const float* __restrict__ ad1) {
    int t = threadIdx.x;
    if (t < 24) {
        int k = t >> 2, h = t & 3;
        float s = 0.f;
        for (int c = 0; c < 64; c++) s += W1[k*C1 + h*64 + c] * as1[h*64 + c];
        g_wsrc[t] = s;
    } else if (t >= 32 && t < 56) {
        int i = t - 32, k = i >> 2, h = i & 3;
        float s = 0.f;
        for (int c = 0; c < 64; c++) s += W1[k*C1 + h*64 + c] * ad1[h*64 + c];
        g_wdst[i] = s;
    }
}

__global__ void k_att1(const float* __restrict__ x) {
    int n = blockIdx.x*blockDim.x + threadIdx.x;
    if (n >= N_NODES) return;
    float2 xa = *(const float2*)&x[n*6];
    float2 xb = *(const float2*)&x[n*6 + 2];
    float2 xc = *(const float2*)&x[n*6 + 4];
    float xv[6] = {xa.x, xa.y, xb.x, xb.y, xc.x, xc.y};
    float s[4] = {0,0,0,0}, d[4] = {0,0,0,0};
    #pragma unroll
    for (int k = 0; k < 6; k++) {
        #pragma unroll
        for (int h = 0; h < 4; h++) {
            s[h] += xv[k]*g_wsrc[k*4+h];
            d[h] += xv[k]*g_wdst[k*4+h];
        }
    }
    *(float4*)&g_asrc1[n*4] = make_float4(s[0],s[1],s[2],s[3]);
    *(float4*)&g_adst1[n*4] = make_float4(d[0],d[1],d[2],d[3]);
    *(float4*)&g_x8[n*8]     = make_float4(xv[0],xv[1],xv[2],xv[3]);
    *(float4*)&g_x8[n*8 + 4] = make_float4(xv[4],xv[5],0.f,0.f);
}

__global__ void k_esum1(const int* __restrict__ ei) {
    int e = blockIdx.x*blockDim.x + threadIdx.x;
    if (e >= ETOT) return;
    int s, d;
    if (e < N_EDGES) { s = ei[e]; d = ei[N_EDGES + e]; } else { s = d = e - N_EDGES; }
    float4 as = *(const float4*)&g_asrc1[s*4];
    float4 ad = *(const float4*)&g_adst1[d*4];
    float ex[4];
    ex[0] = expf(lrelu(as.x + ad.x));
    ex[1] = expf(lrelu(as.y + ad.y));
    ex[2] = expf(lrelu(as.z + ad.z));
    ex[3] = expf(lrelu(as.w + ad.w));
    float4 xa = *(const float4*)&g_x8[s*8];
    float4 xb = *(const float4*)&g_x8[s*8 + 4];
    float* base = &g_xagg[d*32];
    #pragma unroll
    for (int h = 0; h < 4; h++) {
        float w = ex[h];
        redAdd4(base + h*8,     w*xa.x, w*xa.y, w*xa.z, w*xa.w);
        redAdd4(base + h*8 + 4, w*xb.x, w*xb.y, w,      0.f);
    }
}

// fused: h1 = elu(bn(xagg@W1/denom)); hproj2 = h1@W2; att2 dots.
// 64 nodes/block; thread = (node, 32-col half); warp-uniform jc -> broadcast weights.
__global__ void __launch_bounds__(128, 2) k_proj2f(
        const float* __restrict__ W1, const float* __restrict__ b1,
        const float* __restrict__ g1, const float* __restrict__ be1,
        const float* __restrict__ W2,
        const float* __restrict__ as2, const float* __restrict__ ad2) {
    extern __shared__ float sm[];
    float* sW2  = sm;                  // [256][64] = 16384
    float* sW1p = sm + 16384;          // [256][8]: {w0..w5, A, C}
    float* sAs  = sW1p + 2048;         // 64
    float* sAd  = sAs + 64;            // 64
    float* sS   = sAd + 64;            // 128
    float* sD   = sS + 128;            // 128
    int t = threadIdx.x;
    int nbase = blockIdx.x * 64;
    int jc = t >> 6;                   // warp-uniform column half
    int nl = t & 63;                   // local node
    int n  = nbase + nl;

    for (int i = t; i < 16384; i += 128) sW2[i] = W2[i];
    for (int i = t; i < 2048; i += 128) {
        int c = i >> 3, r = i & 7;
        float v;
        if (r < 6)      v = W1[r*C1 + c];
        else if (r == 6) v = g1[c]*BN_INV;
        else { float A = g1[c]*BN_INV; v = A*b1[c] + be1[c]; }
        sW1p[i] = v;
    }
    if (t < 64)       sAs[t] = as2[t];
    else              sAd[t-64] = ad2[t-64];
    __syncthreads();

    // xagg row into registers, pre-scaled by 1/denom per head
    float xr[24];
    #pragma unroll
    for (int h = 0; h < 4; h++) {
        float4 v0 = *(const float4*)&g_xagg[n*32 + h*8];
        float4 v1 = *(const float4*)&g_xagg[n*32 + h*8 + 4];
        float inv = 1.f / v1.z;        // slot 6 = denom
        xr[h*6+0] = v0.x*inv; xr[h*6+1] = v0.y*inv; xr[h*6+2] = v0.z*inv;
        xr[h*6+3] = v0.w*inv; xr[h*6+4] = v1.x*inv; xr[h*6+5] = v1.y*inv;
    }

    float acc[32];
    #pragma unroll
    for (int j = 0; j < 32; j++) acc[j] = 0.f;

    #pragma unroll
    for (int h = 0; h < 4; h++) {
        float x0 = xr[h*6+0], x1 = xr[h*6+1], x2 = xr[h*6+2];
        float x3 = xr[h*6+3], x4 = xr[h*6+4], x5 = xr[h*6+5];
        #pragma unroll 2
        for (int k2 = 0; k2 < 64; k2++) {
            int k = h*64 + k2;
            float4 wa = *(const float4*)&sW1p[k*8];
            float4 wb = *(const float4*)&sW1p[k*8 + 4];
            float dot = x0*wa.x + x1*wa.y + x2*wa.z + x3*wa.w + x4*wb.x + x5*wb.y;
            float v = eluf(dot*wb.z + wb.w);
            const float4* wr = (const float4*)&sW2[k*64 + jc*32];
            #pragma unroll
            for (int j4 = 0; j4 < 8; j4++) {
                float4 w = wr[j4];
                acc[4*j4+0] = fmaf(v, w.x, acc[4*j4+0]);
                acc[4*j4+1] = fmaf(v, w.y, acc[4*j4+1]);
                acc[4*j4+2] = fmaf(v, w.z, acc[4*j4+2]);
                acc[4*j4+3] = fmaf(v, w.w, acc[4*j4+3]);
            }
        }
    }

    float s = 0.f, dd = 0.f;
    #pragma unroll
    for (int j4 = 0; j4 < 8; j4++) {
        *(float4*)&g_hproj2[n*64 + jc*32 + j4*4] =
            make_float4(acc[4*j4], acc[4*j4+1], acc[4*j4+2], acc[4*j4+3]);
        #pragma unroll
        for (int u = 0; u < 4; u++) {
            s  += acc[4*j4+u]*sAs[jc*32 + j4*4 + u];
            dd += acc[4*j4+u]*sAd[jc*32 + j4*4 + u];
        }
    }
    sS[nl*2 + jc] = s;
    sD[nl*2 + jc] = dd;
    __syncthreads();
    if (t < 64) {
        g_asrc2[nbase + t] = sS[t*2] + sS[t*2+1];
        g_adst2[nbase + t] = sD[t*2] + sD[t*2+1];
    }
}

// 8 threads/edge: denom += ex; accum2[dst] += ex*hproj2[src]
__global__ void k_esum2(const int* __restrict__ ei) {
    int gt = blockIdx.x*blockDim.x + threadIdx.x;
    int e = gt >> 3, q = gt & 7;
    if (e >= ETOT) return;
    int s, d;
    if (e < N_EDGES) { s = ei[e]; d = ei[N_EDGES + e]; } else { s = d = e - N_EDGES; }
    float ex = expf(lrelu(g_asrc2[s] + g_adst2[d]));
    if (q == 0) atomicAdd(&g_denom2[d], ex);
    int c = q*8;
    float4 v1 = *(const float4*)&g_hproj2[s*64 + c];
    float4 v2 = *(const float4*)&g_hproj2[s*64 + c + 4];
    redAdd4(&g_accum2[d*64 + c],     v1.x*ex, v1.y*ex, v1.z*ex, v1.w*ex);
    redAdd4(&g_accum2[d*64 + c + 4], v2.x*ex, v2.y*ex, v2.z*ex, v2.w*ex);
}

// fused: h2 = elu(bn(accum2/denom2)) staged ONCE in smem; xgates = h2@Wih^T + biases.
// 32 nodes/block; thread = (node, 64-col chunk); warp-uniform jc -> broadcast weights.
__global__ void __launch_bounds__(128, 2) k_xgates2(
        const float* __restrict__ Wih, const float* __restrict__ bih,
        const float* __restrict__ bhh, const float* __restrict__ b2,
        const float* __restrict__ g2, const float* __restrict__ be2,
        const int* __restrict__ batch, const int* __restrict__ ntime) {
    extern __shared__ float sm[];
    float* sWT   = sm;                 // [64 k][256 j] = Wih^T, 16384
    float* h2s   = sm + 16384;         // [32][65] = 2080 (conflict-free stride)
    float* sBias = h2s + 2080;         // 256: bih+bhh
    float* sA2   = sBias + 256;        // 64
    float* sC2   = sA2 + 64;           // 64
    float* sInv  = sC2 + 64;           // 32
    int t = threadIdx.x;
    int nbase = blockIdx.x * 32;
    int jc = t >> 5;                   // warp-uniform column chunk (0..3)
    int nl = t & 31;                   // local node = lane

    for (int i = t; i < 16384; i += 128) {
        int j = i >> 6, k = i & 63;
        sWT[k*256 + j] = Wih[i];
    }
    for (int i = t; i < 256; i += 128) sBias[i] = bih[i] + bhh[i];
    if (t < 64) {
        float A = g2[t]*BN_INV;
        sA2[t] = A;
        sC2[t] = A*b2[t] + be2[t];
    } else if (t < 96) {
        sInv[t-64] = 1.f / g_denom2[nbase + (t-64)];
    }
    __syncthreads();

    // stage h2 (elu once per element)
    for (int i = t; i < 32*64; i += 128) {
        int nn = i >> 6, k = i & 63;
        float v = g_accum2[(nbase + nn)*64 + k] * sInv[nn];
        h2s[nn*65 + k] = eluf(v*sA2[k] + sC2[k]);
    }
    __syncthreads();

    float acc[64];
    #pragma unroll
    for (int j = 0; j < 64; j++) acc[j] = 0.f;

    const float* hrow = &h2s[nl*65];
    #pragma unroll 2
    for (int k = 0; k < 64; k++) {
        float v = hrow[k];
        const float4* wr = (const float4*)&sWT[k*256 + jc*64];
        #pragma unroll
        for (int j4 = 0; j4 < 16; j4++) {
            float4 w = wr[j4];
            acc[4*j4+0] = fmaf(v, w.x, acc[4*j4+0]);
            acc[4*j4+1] = fmaf(v, w.y, acc[4*j4+1]);
            acc[4*j4+2] = fmaf(v, w.z, acc[4*j4+2]);
            acc[4*j4+3] = fmaf(v, w.w, acc[4*j4+3]);
        }
    }

    int n = nbase + nl;
    int dest = (ntime[n]*G_GRAPHS + batch[n])*C1 + jc*64;
    #pragma unroll
    for (int j4 = 0; j4 < 16; j4++) {
        int j = jc*64 + j4*4;
        *(float4*)&g_xgates[dest + j4*4] =
            make_float4(acc[4*j4]+sBias[j],     acc[4*j4+1]+sBias[j+1],
                        acc[4*j4+2]+sBias[j+2], acc[4*j4+3]+sBias[j+3]);
    }
}

// LSTM: 1 graph/block (512 blocks), Whh row in regs, xgates prefetch, fused FC.
__global__ void __launch_bounds__(256) k_lstm(
        const float* __restrict__ Whh, const float* __restrict__ Wfc,
        const float* __restrict__ bfc, float* __restrict__ out) {
    __shared__ float hhs[64];
    __shared__ float gates[C1];
    int t = threadIdx.x;
    int g = blockIdx.x;

    unsigned long long w2[32];
    const float4* wrow = (const float4*)(Whh + t*64);
    #pragma unroll
    for (int i = 0; i < 16; i++) {
        float4 w = wrow[i];
        w2[2*i]   = pk(w.x, w.y);
        w2[2*i+1] = pk(w.z, w.w);
    }
    if (t < 64) hhs[t] = 0.f;
    float c = 0.f;
    float xg_cur = g_xgates[g*C1 + t];
    __syncthreads();

    for (int step = 0; step < T_STEPS; step++) {
        float xg_next = 0.f;
        if (step + 1 < T_STEPS) xg_next = g_xgates[((step+1)*G_GRAPHS + g)*C1 + t];
        unsigned long long aA = 0ull, aB = 0ull;
        #pragma unroll
        for (int k2 = 0; k2 < 16; k2++) {
            ulonglong2 hv = *(const ulonglong2*)&hhs[k2*4];
            ffma2(aA, hv.x, w2[2*k2]);
            ffma2(aB, hv.y, w2[2*k2+1]);
        }
        float2 a = unpk(aA), b = unpk(aB);
        gates[t] = xg_cur + a.x + a.y + b.x + b.y;
        __syncthreads();
        if (t < 64) {
            float ig = gates[t],       fg = gates[64 + t];
            float gg = gates[128 + t], og = gates[192 + t];
            c = sigf(fg)*c + sigf(ig)*tanhf(gg);
            hhs[t] = sigf(og)*tanhf(c);
        }
        __syncthreads();
        xg_cur = xg_next;
    }
    if (t < OUT_DIM) {
        float acc = bfc[t];
        #pragma unroll 8
        for (int k = 0; k < 64; k++) acc += hhs[k] * Wfc[k*OUT_DIM + t];
        out[g*OUT_DIM + t] = acc;
    }
}

// ---------------- launch ----------------
static const int SMEM_P2 = (16384 + 2048 + 64 + 64 + 128 + 128) * 4;        // 75264 B
static const int SMEM_XG = (16384 + 2080 + 256 + 64 + 64 + 32) * 4;         // 75520 B

extern "C" void kernel_launch(void* const* d_in, const int* in_sizes, int n_in,
                              void* d_out, int out_size) {
    const float* x    = (const float*)d_in[0];
    const int*   ei   = (const int*)  d_in[1];
    const int*   batch= (const int*)  d_in[2];
    const int*   ntime= (const int*)  d_in[3];
    const float* W1   = (const float*)d_in[4];
    const float* as1  = (const float*)d_in[5];
    const float* ad1  = (const float*)d_in[6];
    const float* b1   = (const float*)d_in[7];
    const float* g1   = (const float*)d_in[8];
    const float* be1  = (const float*)d_in[9];
    const float* W2   = (const float*)d_in[10];
    const float* as2  = (const float*)d_in[11];
    const float* ad2  = (const float*)d_in[12];
    const float* b2   = (const float*)d_in[13];
    const float* g2   = (const float*)d_in[14];
    const float* be2  = (const float*)d_in[15];
    const float* Wih  = (const float*)d_in[16];
    const float* Whh  = (const float*)d_in[17];
    const float* bih  = (const float*)d_in[18];
    const float* bhh  = (const float*)d_in[19];
    const float* Wfc  = (const float*)d_in[20];
    const float* bfc  = (const float*)d_in[21];
    float* out = (float*)d_out;

    cudaFuncSetAttribute(k_proj2f,  cudaFuncAttributeMaxDynamicSharedMemorySize, SMEM_P2);
    cudaFuncSetAttribute(k_xgates2, cudaFuncAttributeMaxDynamicSharedMemorySize, SMEM_XG);

    void *p_xagg, *p_acc2, *p_den2;
    cudaGetSymbolAddress(&p_xagg, g_xagg);
    cudaGetSymbolAddress(&p_acc2, g_accum2);
    cudaGetSymbolAddress(&p_den2, g_denom2);
    cudaMemsetAsync(p_xagg, 0, sizeof(float)*N_NODES*32);
    cudaMemsetAsync(p_acc2, 0, sizeof(float)*N_NODES*HID);
    cudaMemsetAsync(p_den2, 0, sizeof(float)*N_NODES);

    k_pre1   <<<1, 64>>>(W1, as1, ad1);
    k_att1   <<<(N_NODES + 255)/256, 256>>>(x);
    k_esum1  <<<(ETOT + 255)/256, 256>>>(ei);
    k_proj2f <<<N_NODES/64, 128, SMEM_P2>>>(W1, b1, g1, be1, W2, as2, ad2);
    k_esum2  <<<(ETOT*8 + 255)/256, 256>>>(ei);
    k_xgates2<<<N_NODES/32, 128, SMEM_XG>>>(Wih, bih, bhh, b2, g2, be2, batch, ntime);
    k_lstm   <<<G_GRAPHS, 256>>>(Whh, Wfc, bfc, out);
}

// round 9
// speedup vs baseline: 1.0661x; 1.0298x over previous
#include <cuda_runtime.h>
#include <math.h>

#define N_NODES 25600
#define N_EDGES 204800
#define ETOT    (N_EDGES + N_NODES)   // 230400
#define IN_CH   6
#define HID     64
#define HEADS   4
#define C1      (HEADS*HID)           // 256
#define G_GRAPHS 512
#define T_STEPS  50
#define OUT_DIM  30
#define NEG_SLOPE 0.2f
#define BN_INV 0.9999950000374996f    // 1/sqrt(1+1e-5)

// ---------------- scratch ----------------
__device__ float g_wsrc[24];                  // [k][h]
__device__ float g_wdst[24];
__device__ __align__(16) float g_x8[N_NODES*8];       // padded x rows
__device__ __align__(16) float g_asrc1[N_NODES*4];
__device__ __align__(16) float g_adst1[N_NODES*4];
__device__ __align__(16) float g_xagg[N_NODES*32];    // 4 heads x [x0..x5, denom, 0]
__device__ __align__(16) float g_hproj2[N_NODES*HID];
__device__ float g_asrc2[N_NODES];
__device__ float g_adst2[N_NODES];
__device__ float g_denom2[N_NODES];
__device__ __align__(16) float g_accum2[N_NODES*HID];
__device__ __align__(16) float g_xgates[N_NODES*C1];  // (t, g, 256)

// ---------------- helpers ----------------
__device__ __forceinline__ float lrelu(float v) { return v > 0.f ? v : NEG_SLOPE*v; }
__device__ __forceinline__ float eluf(float v)  { return v > 0.f ? v : (__expf(v) - 1.f); }
__device__ __forceinline__ float sigf(float v)  { return 1.f/(1.f+expf(-v)); }

__device__ __forceinline__ void redAdd4(float* addr, float a, float b, float c, float d) {
    asm volatile("red.global.add.v4.f32 [%0], {%1,%2,%3,%4};"
                 :: "l"(addr), "f"(a), "f"(b), "f"(c), "f"(d) : "memory");
}
__device__ __forceinline__ void ffma2(unsigned long long& d, unsigned long long a,
                                      unsigned long long b) {
    asm("fma.rn.f32x2 %0, %1, %2, %0;" : "+l"(d) : "l"(a), "l"(b));
}
__device__ __forceinline__ unsigned long long pk(float a, float b) {
    unsigned long long r;
    asm("mov.b64 %0, {%1, %2};" : "=l"(r) : "f"(a), "f"(b));
    return r;
}
__device__ __forceinline__ float2 unpk(unsigned long long v) {
    float2 r;
    asm("mov.b64 {%0, %1}, %2;" : "=f"(r.x), "=f"(r.y) : "l"(v));
    return r;
}

// ---------------- kernels ----------------
__global__ void k_pre1(const float* __restrict__ W1, const float* __restrict__ as1,
                       const float* __restrict__ ad1) {
    int t = threadIdx.x;
    if (t < 24) {
        int k = t >> 2, h = t & 3;
        float s = 0.f;
        for (int c = 0; c < 64; c++) s += W1[k*C1 + h*64 + c] * as1[h*64 + c];
        g_wsrc[t] = s;
    } else if (t >= 32 && t < 56) {
        int i = t - 32, k = i >> 2, h = i & 3;
        float s = 0.f;
        for (int c = 0; c < 64; c++) s += W1[k*C1 + h*64 + c] * ad1[h*64 + c];
        g_wdst[i] = s;
    }
}

__global__ void k_att1(const float* __restrict__ x) {
    int n = blockIdx.x*blockDim.x + threadIdx.x;
    if (n >= N_NODES) return;
    float2 xa = *(const float2*)&x[n*6];
    float2 xb = *(const float2*)&x[n*6 + 2];
    float2 xc = *(const float2*)&x[n*6 + 4];
    float xv[6] = {xa.x, xa.y, xb.x, xb.y, xc.x, xc.y};
    float s[4] = {0,0,0,0}, d[4] = {0,0,0,0};
    #pragma unroll
    for (int k = 0; k < 6; k++) {
        #pragma unroll
        for (int h = 0; h < 4; h++) {
            s[h] += xv[k]*g_wsrc[k*4+h];
            d[h] += xv[k]*g_wdst[k*4+h];
        }
    }
    *(float4*)&g_asrc1[n*4] = make_float4(s[0],s[1],s[2],s[3]);
    *(float4*)&g_adst1[n*4] = make_float4(d[0],d[1],d[2],d[3]);
    *(float4*)&g_x8[n*8]     = make_float4(xv[0],xv[1],xv[2],xv[3]);
    *(float4*)&g_x8[n*8 + 4] = make_float4(xv[4],xv[5],0.f,0.f);
}

__global__ void k_esum1(const int* __restrict__ ei) {
    int e = blockIdx.x*blockDim.x + threadIdx.x;
    if (e >= ETOT) return;
    int s, d;
    if (e < N_EDGES) { s = ei[e]; d = ei[N_EDGES + e]; } else { s = d = e - N_EDGES; }
    float4 as = *(const float4*)&g_asrc1[s*4];
    float4 ad = *(const float4*)&g_adst1[d*4];
    float ex[4];
    ex[0] = expf(lrelu(as.x + ad.x));
    ex[1] = expf(lrelu(as.y + ad.y));
    ex[2] = expf(lrelu(as.z + ad.z));
    ex[3] = expf(lrelu(as.w + ad.w));
    float4 xa = *(const float4*)&g_x8[s*8];
    float4 xb = *(const float4*)&g_x8[s*8 + 4];
    float* base = &g_xagg[d*32];
    #pragma unroll
    for (int h = 0; h < 4; h++) {
        float w = ex[h];
        redAdd4(base + h*8,     w*xa.x, w*xa.y, w*xa.z, w*xa.w);
        redAdd4(base + h*8 + 4, w*xb.x, w*xb.y, w,      0.f);
    }
}

// fused: h1 = elu(bn(xagg@W1/denom)); hproj2 = h1@W2; att2 dots.
// 64 nodes/block; thread = (node, 32-col half); warp-uniform jc -> broadcast weights.
// Column-pair SIMD via fma.rn.f32x2.
__global__ void __launch_bounds__(128, 3) k_proj2f(
        const float* __restrict__ W1, const float* __restrict__ b1,
        const float* __restrict__ g1, const float* __restrict__ be1,
        const float* __restrict__ W2,
        const float* __restrict__ as2, const float* __restrict__ ad2) {
    extern __shared__ float sm[];
    float* sW2  = sm;                  // [256][64] = 16384
    float* sW1p = sm + 16384;          // [256][8]: {w0..w5, A, C}
    float* sAs  = sW1p + 2048;         // 64
    float* sAd  = sAs + 64;            // 64
    float* sS   = sAd + 64;            // 128
    float* sD   = sS + 128;            // 128
    int t = threadIdx.x;
    int nbase = blockIdx.x * 64;
    int jc = t >> 6;                   // warp-uniform column half
    int nl = t & 63;                   // local node
    int n  = nbase + nl;

    for (int i = t; i < 16384; i += 128) sW2[i] = W2[i];
    for (int i = t; i < 2048; i += 128) {
        int c = i >> 3, r = i & 7;
        float v;
        if (r < 6)      v = W1[r*C1 + c];
        else if (r == 6) v = g1[c]*BN_INV;
        else { float A = g1[c]*BN_INV; v = A*b1[c] + be1[c]; }
        sW1p[i] = v;
    }
    if (t < 64)       sAs[t] = as2[t];
    else              sAd[t-64] = ad2[t-64];
    __syncthreads();

    // xagg row into registers, pre-scaled by 1/denom per head
    float xr[24];
    #pragma unroll
    for (int h = 0; h < 4; h++) {
        float4 v0 = *(const float4*)&g_xagg[n*32 + h*8];
        float4 v1 = *(const float4*)&g_xagg[n*32 + h*8 + 4];
        float inv = 1.f / v1.z;        // slot 6 = denom
        xr[h*6+0] = v0.x*inv; xr[h*6+1] = v0.y*inv; xr[h*6+2] = v0.z*inv;
        xr[h*6+3] = v0.w*inv; xr[h*6+4] = v1.x*inv; xr[h*6+5] = v1.y*inv;
    }

    unsigned long long acc2[16];       // 16 col-pairs = 32 cols
    #pragma unroll
    for (int j = 0; j < 16; j++) acc2[j] = 0ull;

    #pragma unroll
    for (int h = 0; h < 4; h++) {
        float x0 = xr[h*6+0], x1 = xr[h*6+1], x2 = xr[h*6+2];
        float x3 = xr[h*6+3], x4 = xr[h*6+4], x5 = xr[h*6+5];
        #pragma unroll 2
        for (int k2 = 0; k2 < 64; k2++) {
            int k = h*64 + k2;
            float4 wa = *(const float4*)&sW1p[k*8];
            float4 wb = *(const float4*)&sW1p[k*8 + 4];
            float dot = x0*wa.x + x1*wa.y + x2*wa.z + x3*wa.w + x4*wb.x + x5*wb.y;
            float v = eluf(dot*wb.z + wb.w);
            unsigned long long vv = pk(v, v);
            const ulonglong2* wr = (const ulonglong2*)&sW2[k*64 + jc*32];
            #pragma unroll
            for (int w4 = 0; w4 < 8; w4++) {
                ulonglong2 ww = wr[w4];
                ffma2(acc2[2*w4],   vv, ww.x);
                ffma2(acc2[2*w4+1], vv, ww.y);
            }
        }
    }

    float s = 0.f, dd = 0.f;
    #pragma unroll
    for (int w4 = 0; w4 < 8; w4++) {
        float2 u0 = unpk(acc2[2*w4]);
        float2 u1 = unpk(acc2[2*w4+1]);
        *(float4*)&g_hproj2[n*64 + jc*32 + w4*4] = make_float4(u0.x, u0.y, u1.x, u1.y);
        int jb = jc*32 + w4*4;
        s  += u0.x*sAs[jb] + u0.y*sAs[jb+1] + u1.x*sAs[jb+2] + u1.y*sAs[jb+3];
        dd += u0.x*sAd[jb] + u0.y*sAd[jb+1] + u1.x*sAd[jb+2] + u1.y*sAd[jb+3];
    }
    sS[nl*2 + jc] = s;
    sD[nl*2 + jc] = dd;
    __syncthreads();
    if (t < 64) {
        g_asrc2[nbase + t] = sS[t*2] + sS[t*2+1];
        g_adst2[nbase + t] = sD[t*2] + sD[t*2+1];
    }
}

// 8 threads/edge: denom += ex; accum2[dst] += ex*hproj2[src]
__global__ void k_esum2(const int* __restrict__ ei) {
    int gt = blockIdx.x*blockDim.x + threadIdx.x;
    int e = gt >> 3, q = gt & 7;
    if (e >= ETOT) return;
    int s, d;
    if (e < N_EDGES) { s = ei[e]; d = ei[N_EDGES + e]; } else { s = d = e - N_EDGES; }
    float ex = expf(lrelu(g_asrc2[s] + g_adst2[d]));
    if (q == 0) atomicAdd(&g_denom2[d], ex);
    int c = q*8;
    float4 v1 = *(const float4*)&g_hproj2[s*64 + c];
    float4 v2 = *(const float4*)&g_hproj2[s*64 + c + 4];
    redAdd4(&g_accum2[d*64 + c],     v1.x*ex, v1.y*ex, v1.z*ex, v1.w*ex);
    redAdd4(&g_accum2[d*64 + c + 4], v2.x*ex, v2.y*ex, v2.z*ex, v2.w*ex);
}

// fused: h2 = elu(bn(accum2/denom2)) staged ONCE in smem; xgates = h2@Wih^T + biases.
// 32 nodes/block; thread = (node, 64-col chunk); warp-uniform jc -> broadcast weights.
// Column-pair SIMD via fma.rn.f32x2.
__global__ void __launch_bounds__(128, 3) k_xgates2(
        const float* __restrict__ Wih, const float* __restrict__ bih,
        const float* __restrict__ bhh, const float* __restrict__ b2,
        const float* __restrict__ g2, const float* __restrict__ be2,
        const int* __restrict__ batch, const int* __restrict__ ntime) {
    extern __shared__ float sm[];
    float* sWT   = sm;                 // [64 k][256 j] = Wih^T, 16384
    float* h2s   = sm + 16384;         // [32][65] = 2080 (conflict-free stride)
    float* sBias = h2s + 2080;         // 256: bih+bhh
    float* sA2   = sBias + 256;        // 64
    float* sC2   = sA2 + 64;           // 64
    float* sInv  = sC2 + 64;           // 32
    int t = threadIdx.x;
    int nbase = blockIdx.x * 32;
    int jc = t >> 5;                   // warp-uniform column chunk (0..3)
    int nl = t & 31;                   // local node = lane

    for (int i = t; i < 16384; i += 128) {
        int j = i >> 6, k = i & 63;
        sWT[k*256 + j] = Wih[i];
    }
    for (int i = t; i < 256; i += 128) sBias[i] = bih[i] + bhh[i];
    if (t < 64) {
        float A = g2[t]*BN_INV;
        sA2[t] = A;
        sC2[t] = A*b2[t] + be2[t];
    } else if (t < 96) {
        sInv[t-64] = 1.f / g_denom2[nbase + (t-64)];
    }
    __syncthreads();

    // stage h2 (elu once per element)
    for (int i = t; i < 32*64; i += 128) {
        int nn = i >> 6, k = i & 63;
        float v = g_accum2[(nbase + nn)*64 + k] * sInv[nn];
        h2s[nn*65 + k] = eluf(v*sA2[k] + sC2[k]);
    }
    __syncthreads();

    unsigned long long acc2[32];       // 32 col-pairs = 64 cols
    #pragma unroll
    for (int j = 0; j < 32; j++) acc2[j] = 0ull;

    const float* hrow = &h2s[nl*65];
    #pragma unroll 2
    for (int k = 0; k < 64; k++) {
        float v = hrow[k];
        unsigned long long vv = pk(v, v);
        const ulonglong2* wr = (const ulonglong2*)&sWT[k*256 + jc*64];
        #pragma unroll
        for (int w4 = 0; w4 < 16; w4++) {
            ulonglong2 ww = wr[w4];
            ffma2(acc2[2*w4],   vv, ww.x);
            ffma2(acc2[2*w4+1], vv, ww.y);
        }
    }

    int n = nbase + nl;
    int dest = (ntime[n]*G_GRAPHS + batch[n])*C1 + jc*64;
    #pragma unroll
    for (int w4 = 0; w4 < 16; w4++) {
        float2 u0 = unpk(acc2[2*w4]);
        float2 u1 = unpk(acc2[2*w4+1]);
        int j = jc*64 + w4*4;
        *(float4*)&g_xgates[dest + w4*4] =
            make_float4(u0.x+sBias[j],   u0.y+sBias[j+1],
                        u1.x+sBias[j+2], u1.y+sBias[j+3]);
    }
}

// LSTM: 1 graph/block (512 blocks), Whh row in regs, xgates prefetch, fused FC.
__global__ void __launch_bounds__(256) k_lstm(
        const float* __restrict__ Whh, const float* __restrict__ Wfc,
        const float* __restrict__ bfc, float* __restrict__ out) {
    __shared__ float hhs[64];
    __shared__ float gates[C1];
    int t = threadIdx.x;
    int g = blockIdx.x;

    unsigned long long w2[32];
    const float4* wrow = (const float4*)(Whh + t*64);
    #pragma unroll
    for (int i = 0; i < 16; i++) {
        float4 w = wrow[i];
        w2[2*i]   = pk(w.x, w.y);
        w2[2*i+1] = pk(w.z, w.w);
    }
    if (t < 64) hhs[t] = 0.f;
    float c = 0.f;
    float xg_cur = g_xgates[g*C1 + t];
    __syncthreads();

    for (int step = 0; step < T_STEPS; step++) {
        float xg_next = 0.f;
        if (step + 1 < T_STEPS) xg_next = g_xgates[((step+1)*G_GRAPHS + g)*C1 + t];
        unsigned long long aA = 0ull, aB = 0ull;
        #pragma unroll
        for (int k2 = 0; k2 < 16; k2++) {
            ulonglong2 hv = *(const ulonglong2*)&hhs[k2*4];
            ffma2(aA, hv.x, w2[2*k2]);
            ffma2(aB, hv.y, w2[2*k2+1]);
        }
        float2 a = unpk(aA), b = unpk(aB);
        gates[t] = xg_cur + a.x + a.y + b.x + b.y;
        __syncthreads();
        if (t < 64) {
            float ig = gates[t],       fg = gates[64 + t];
            float gg = gates[128 + t], og = gates[192 + t];
            c = sigf(fg)*c + sigf(ig)*tanhf(gg);
            hhs[t] = sigf(og)*tanhf(c);
        }
        __syncthreads();
        xg_cur = xg_next;
    }
    if (t < OUT_DIM) {
        float acc = bfc[t];
        #pragma unroll 8
        for (int k = 0; k < 64; k++) acc += hhs[k] * Wfc[k*OUT_DIM + t];
        out[g*OUT_DIM + t] = acc;
    }
}

// ---------------- launch ----------------
static const int SMEM_P2 = (16384 + 2048 + 64 + 64 + 128 + 128) * 4;        // 75264 B
static const int SMEM_XG = (16384 + 2080 + 256 + 64 + 64 + 32) * 4;         // 75520 B

extern "C" void kernel_launch(void* const* d_in, const int* in_sizes, int n_in,
                              void* d_out, int out_size) {
    const float* x    = (const float*)d_in[0];
    const int*   ei   = (const int*)  d_in[1];
    const int*   batch= (const int*)  d_in[2];
    const int*   ntime= (const int*)  d_in[3];
    const float* W1   = (const float*)d_in[4];
    const float* as1  = (const float*)d_in[5];
    const float* ad1  = (const float*)d_in[6];
    const float* b1   = (const float*)d_in[7];
    const float* g1   = (const float*)d_in[8];
    const float* be1  = (const float*)d_in[9];
    const float* W2   = (const float*)d_in[10];
    const float* as2  = (const float*)d_in[11];
    const float* ad2  = (const float*)d_in[12];
    const float* b2   = (const float*)d_in[13];
    const float* g2   = (const float*)d_in[14];
    const float* be2  = (const float*)d_in[15];
    const float* Wih  = (const float*)d_in[16];
    const float* Whh  = (const float*)d_in[17];
    const float* bih  = (const float*)d_in[18];
    const float* bhh  = (const float*)d_in[19];
    const float* Wfc  = (const float*)d_in[20];
    const float* bfc  = (const float*)d_in[21];
    float* out = (float*)d_out;

    cudaFuncSetAttribute(k_proj2f,  cudaFuncAttributeMaxDynamicSharedMemorySize, SMEM_P2);
    cudaFuncSetAttribute(k_xgates2, cudaFuncAttributeMaxDynamicSharedMemorySize, SMEM_XG);

    void *p_xagg, *p_acc2, *p_den2;
    cudaGetSymbolAddress(&p_xagg, g_xagg);
    cudaGetSymbolAddress(&p_acc2, g_accum2);
    cudaGetSymbolAddress(&p_den2, g_denom2);
    cudaMemsetAsync(p_xagg, 0, sizeof(float)*N_NODES*32);
    cudaMemsetAsync(p_acc2, 0, sizeof(float)*N_NODES*HID);
    cudaMemsetAsync(p_den2, 0, sizeof(float)*N_NODES);

    k_pre1   <<<1, 64>>>(W1, as1, ad1);
    k_att1   <<<(N_NODES + 255)/256, 256>>>(x);
    k_esum1  <<<(ETOT + 255)/256, 256>>>(ei);
    k_proj2f <<<N_NODES/64, 128, SMEM_P2>>>(W1, b1, g1, be1, W2, as2, ad2);
    k_esum2  <<<(ETOT*8 + 255)/256, 256>>>(ei);
    k_xgates2<<<N_NODES/32, 128, SMEM_XG>>>(Wih, bih, bhh, b2, g2, be2, batch, ntime);
    k_lstm   <<<G_GRAPHS, 256>>>(Whh, Wfc, bfc, out);
}